// round 11
// baseline (speedup 1.0000x reference)
#include <cuda_runtime.h>
#include <cstdint>

#define NN 50000
#define NE 800000
#define F  64
#define NLAYERS 3
#define NCHUNKS 196     // ceil(NN/256)

#define TE  64          // edges per block in edge kernel
#define PAD 68          // h1s/h2n row pad in floats (272B, 16B-aligned)
#define WST 144         // W2p row stride in floats (swizzled)

// ---------------- scratch (device globals; no allocation allowed) ----------
__device__ float g_u [NN * F];
__device__ float g_v [NN * F];
__device__ float g_x1[NN * F];
__device__ float g_x2[NN * F];
__device__ int   g_cnt [NN];
__device__ int   g_part[NN];
__device__ int   g_run [NN];
__device__ int   g_bsum[256];
__device__ int   g_ssrc[NE];
__device__ int   g_sdst[NE];

// ===========================================================================
// Prep: counting sort of edges by dst (once per launch)
// ===========================================================================
__global__ __launch_bounds__(256) void hist_kernel(const int* __restrict__ ei,
                                                   int* __restrict__ cnt)
{
    int e = blockIdx.x * 256 + threadIdx.x;
    atomicAdd(&cnt[ei[NE + e]], 1);
}

__device__ __forceinline__ int block_scan_excl(int v, int t, int* wsum)
{
    int lane = t & 31, w = t >> 5;
    int s = v;
    #pragma unroll
    for (int d = 1; d < 32; d <<= 1) {
        int n = __shfl_up_sync(0xffffffffu, s, d);
        if (lane >= d) s += n;
    }
    if (lane == 31) wsum[w] = s;
    __syncthreads();
    if (w == 0) {
        int ws = (lane < 8) ? wsum[lane] : 0;
        #pragma unroll
        for (int d = 1; d < 8; d <<= 1) {
            int n = __shfl_up_sync(0xffffffffu, ws, d);
            if (lane >= d) ws += n;
        }
        if (lane < 8) wsum[lane] = ws;
    }
    __syncthreads();
    int base = (w > 0) ? wsum[w - 1] : 0;
    return s - v + base;
}

__global__ __launch_bounds__(256) void scan1_kernel(const int* __restrict__ cnt,
                                                    int* __restrict__ part,
                                                    int* __restrict__ bsum)
{
    __shared__ int wsum[8];
    int t = threadIdx.x;
    int i = blockIdx.x * 256 + t;
    int v = (i < NN) ? cnt[i] : 0;
    int ex = block_scan_excl(v, t, wsum);
    if (i < NN) part[i] = ex;
    if (t == 255) bsum[blockIdx.x] = ex + v;
}

__global__ __launch_bounds__(256) void scan23_kernel(const int* __restrict__ part,
                                                     const int* __restrict__ bsum,
                                                     int* __restrict__ run)
{
    __shared__ int wsum[8];
    __shared__ int sb[256];
    int t = threadIdx.x;
    int v = (t < NCHUNKS) ? bsum[t] : 0;
    int ex = block_scan_excl(v, t, wsum);
    sb[t] = ex;
    __syncthreads();
    #pragma unroll 4
    for (int i = t; i < NN; i += 256)
        run[i] = part[i] + sb[i >> 8];
}

__global__ __launch_bounds__(256) void scatter_kernel(const int* __restrict__ ei,
                                                      int* __restrict__ run,
                                                      int* __restrict__ ssrc,
                                                      int* __restrict__ sdst)
{
    int e = blockIdx.x * 256 + threadIdx.x;
    int s = ei[e];
    int d = ei[NE + e];
    int pos = atomicAdd(&run[d], 1);
    ssrc[pos] = s;
    sdst[pos] = d;
}

// ===========================================================================
// Node kernel: u = x@(W1a - W1b) + b1 ;  v = x@W1b
// x staged DUPLICATED ({x,x} pairs) -> no mov.b64 in inner loop (14 issues
// per 16 pipe-cycles -> fma-bound). Also zero-fills a slice of y.
// ===========================================================================
__global__ __launch_bounds__(256) void node_kernel(
    const float* __restrict__ x,
    const float* __restrict__ W1,   // [128,64]
    const float* __restrict__ b1g,  // [64]
    float* __restrict__ u,
    float* __restrict__ v,
    float* __restrict__ y)
{
    __shared__ float W1s[128 * 64];   // 32KB
    __shared__ float xd[32 * 128];    // 16KB duplicated pairs

    const int t  = threadIdx.x;
    const int n0 = blockIdx.x * 32;

    {
        int base = blockIdx.x * 2048 + t * 8;
        if (base < NN * F) {
            float4 z = make_float4(0.f, 0.f, 0.f, 0.f);
            *(float4*)(y + base)     = z;
            *(float4*)(y + base + 4) = z;
        }
    }

    // stage W1 (vectorized): 2048 float4
    #pragma unroll
    for (int r = 0; r < 8; r++) {
        int j = r * 256 + t;
        *(float4*)&W1s[j * 4] = *(const float4*)&W1[j * 4];
    }

    // stage x duplicated: 512 float4 loads, each expanded to 4 {v,v} pairs
    #pragma unroll
    for (int r = 0; r < 2; r++) {
        int j    = r * 256 + t;        // 0..511
        int nn   = j >> 4;             // node in tile
        int q    = j & 15;             // float4 within row
        int node = n0 + nn;
        float4 xv = (node < NN) ? *(const float4*)&x[node * F + q * 4]
                                : make_float4(0.f, 0.f, 0.f, 0.f);
        float* dst = &xd[nn * 128 + q * 8];
        *(float2*)(dst + 0) = make_float2(xv.x, xv.x);
        *(float2*)(dst + 2) = make_float2(xv.y, xv.y);
        *(float2*)(dst + 4) = make_float2(xv.z, xv.z);
        *(float2*)(dst + 6) = make_float2(xv.w, xv.w);
    }
    __syncthreads();

    const int jc = (t & 31) * 2;
    const int ng = t >> 5;

    unsigned long long accA[4], accC[4];
    #pragma unroll
    for (int s = 0; s < 4; s++) { accA[s] = 0ull; accC[s] = 0ull; }

    #pragma unroll 8
    for (int k = 0; k < F; k++) {
        unsigned long long wa = *(const unsigned long long*)&W1s[k * F + jc];
        unsigned long long wb = *(const unsigned long long*)&W1s[(F + k) * F + jc];
        #pragma unroll
        for (int s = 0; s < 4; s++) {
            unsigned long long hh =
                *(const unsigned long long*)&xd[(ng + 8 * s) * 128 + 2 * k];
            asm("fma.rn.f32x2 %0, %1, %2, %0;" : "+l"(accA[s]) : "l"(hh), "l"(wa));
            asm("fma.rn.f32x2 %0, %1, %2, %0;" : "+l"(accC[s]) : "l"(hh), "l"(wb));
        }
    }

    const float bb0 = b1g[jc], bb1 = b1g[jc + 1];
    #pragma unroll
    for (int s = 0; s < 4; s++) {
        int node = n0 + ng + 8 * s;
        if (node < NN) {
            unsigned a0u, a1u, c0u, c1u;
            asm("mov.b64 {%0, %1}, %2;" : "=r"(a0u), "=r"(a1u) : "l"(accA[s]));
            asm("mov.b64 {%0, %1}, %2;" : "=r"(c0u), "=r"(c1u) : "l"(accC[s]));
            float a0 = __uint_as_float(a0u), a1 = __uint_as_float(a1u);
            float c0 = __uint_as_float(c0u), c1 = __uint_as_float(c1u);
            u[node * F + jc]     = a0 - c0 + bb0;
            u[node * F + jc + 1] = a1 - c1 + bb1;
            v[node * F + jc]     = c0;
            v[node * F + jc + 1] = c1;
        }
    }
}

// ===========================================================================
// Edge kernel (dst-sorted, TE=64 edges/block, 256 threads, 4 blocks/SM):
//  phase1: h1s[e][k] = relu(u[dst]+v[src])  coalesced
//  phase2: k-pair packed f32x2, tile 4 edges x 4 cols (proven R7/R10 loop)
//  phase3: segment-id scan (ballot) -> smem seg_tbl (shared atomicMax) ->
//          ONE global op per (segment,col): STG for block-interior dst,
//          atomicMax only for the block's first/last dst.
// ===========================================================================
__global__ __launch_bounds__(256, 4) void edge_kernel(
    const int* __restrict__ ssrc,
    const int* __restrict__ sdst,
    const float* __restrict__ u,
    const float* __restrict__ v,
    const float* __restrict__ W2,       // [64,64]
    const float* __restrict__ b2g,      // [64]
    float* __restrict__ out)
{
    extern __shared__ float smem[];
    float* hbuf = smem;                       // TE*PAD (h1s, then h2n)
    float* W2p  = smem + TE * PAD;            // 32*WST; later seg_tbl (64*64)
    float* b2s  = W2p + 32 * WST;             // 64; later segid (int)
    int*   si   = (int*)(b2s + 64);           // TE; later seg_dst
    int*   di   = si + TE;                    // TE (live throughout)
    int*   misc = di + TE;                    // 4 ints

    const int t  = threadIdx.x;
    const int e0 = blockIdx.x * TE;

    // stage W2: W2p[k2][swizzle(c) + p] = W2[2*k2+p][c]
    #pragma unroll
    for (int r = 0; r < 4; r++) {
        int j  = r * 256 + t;
        int kk = j >> 4;
        int c0 = (j & 15) * 4;
        float4 w4 = *(const float4*)(W2 + kk * 64 + c0);
        int k2 = kk >> 1, p = kk & 1;
        int cgi = c0 >> 2;
        int base = k2 * WST + cgi * 8 + (cgi >> 2) * 4 + p;
        W2p[base]     = w4.x;
        W2p[base + 2] = w4.y;
        W2p[base + 4] = w4.z;
        W2p[base + 6] = w4.w;
    }
    if (t < 64) b2s[t] = b2g[t];
    if (t < TE)            si[t]      = ssrc[e0 + t];
    else if (t < 2 * TE)   di[t - TE] = sdst[e0 + t - TE];
    __syncthreads();

    // phase 1: h1 = relu(u[dst] + v[src]) -> smem row-major (float4)
    #pragma unroll 4
    for (int r = 0; r < 4; r++) {
        int idx = r * 256 + t;
        int e   = idx >> 4;
        int q   = idx & 15;
        float4 uq = *(const float4*)(u + (size_t)di[e] * F + q * 4);
        float4 vq = *(const float4*)(v + (size_t)si[e] * F + q * 4);
        float4 h;
        h.x = fmaxf(uq.x + vq.x, 0.f);
        h.y = fmaxf(uq.y + vq.y, 0.f);
        h.z = fmaxf(uq.z + vq.z, 0.f);
        h.w = fmaxf(uq.w + vq.w, 0.f);
        *(float4*)&hbuf[e * PAD + q * 4] = h;
    }
    __syncthreads();

    // phase 2: tile = 4 edges x 4 cols, one k-pair per iteration
    const int cg   = t & 15;
    const int eg   = t >> 4;
    const int woff = cg * 8 + (cg >> 2) * 4;

    unsigned long long acc[4][4];
    #pragma unroll
    for (int i = 0; i < 4; i++)
        #pragma unroll
        for (int c = 0; c < 4; c++)
            acc[i][c] = 0ull;

    const float* hrow = hbuf + eg * 4 * PAD;
    #pragma unroll 4
    for (int k2 = 0; k2 < 32; k2++) {
        unsigned long long hp[4];
        #pragma unroll
        for (int i = 0; i < 4; i++)
            hp[i] = *(const unsigned long long*)&hrow[i * PAD + 2 * k2];

        const float* wr = W2p + k2 * WST + woff;
        ulonglong2 w01 = *(const ulonglong2*)wr;
        ulonglong2 w23 = *(const ulonglong2*)(wr + 4);
        unsigned long long wv[4] = {w01.x, w01.y, w23.x, w23.y};

        #pragma unroll
        for (int i = 0; i < 4; i++)
            #pragma unroll
            for (int c = 0; c < 4; c++)
                asm("fma.rn.f32x2 %0, %1, %2, %0;"
                    : "+l"(acc[i][c]) : "l"(hp[i]), "l"(wv[c]));
    }

    // phase 3a: h2 = lo + hi + b2 -> overlaid smem h2n[e][PAD]
    __syncthreads();
    #pragma unroll
    for (int i = 0; i < 4; i++) {
        int e = eg * 4 + i;
        float4 o;
        float* op = (float*)&o;
        #pragma unroll
        for (int c = 0; c < 4; c++) {
            unsigned lo, hi;
            asm("mov.b64 {%0, %1}, %2;" : "=r"(lo), "=r"(hi) : "l"(acc[i][c]));
            op[c] = __uint_as_float(lo) + __uint_as_float(hi) + b2s[cg * 4 + c];
        }
        *(float4*)&hbuf[e * PAD + cg * 4] = o;
    }
    __syncthreads();   // b2s dead from here; W2p dead

    // phase 3b-i: zero seg_tbl (overlay W2p) + raw segment ids via ballot
    float* seg_tbl = W2p;
    int*   sgid    = (int*)b2s;
    int*   sdst2   = si;
    {
        float4 z4 = make_float4(0.f, 0.f, 0.f, 0.f);
        #pragma unroll
        for (int r = 0; r < 4; r++)
            *(float4*)&seg_tbl[(r * 256 + t) * 4] = z4;
    }
    int myflag = 0;
    if (t < TE) {
        int lane = t & 31;
        myflag = (t == 0) || (di[t] != di[t - 1]);
        unsigned bm = __ballot_sync(0xffffffffu, myflag);
        int sid = __popc(bm & (0xffffffffu >> (31 - lane))) - 1;
        if (lane == 31) misc[t >> 5] = __popc(bm);
        sgid[t] = sid;
    }
    __syncthreads();

    const int nseg = misc[0] + misc[1];
    if (t < TE) {
        int off = (t >> 5) ? misc[0] : 0;
        int fs  = sgid[t] + off;
        sgid[t] = fs;
        if (myflag) sdst2[fs] = di[t];
    }
    __syncthreads();

    // phase 3b-ii: segmented max into smem seg_tbl (shared atomicMax)
    {
        const int c  = t & 63;
        const int g  = t >> 6;
        const int r0 = g * 16;
        int   sid = sgid[r0];
        int   cur = di[r0];
        float m   = hbuf[r0 * PAD + c];
        #pragma unroll 1
        for (int r = r0 + 1; r < r0 + 16; r++) {
            int   d2  = di[r];
            float val = hbuf[r * PAD + c];
            if (d2 != cur) {
                atomicMax((unsigned*)&seg_tbl[sid * 64 + c],
                          __float_as_uint(fmaxf(m, 0.f)));
                sid++; cur = d2; m = val;
            } else {
                m = fmaxf(m, val);
            }
        }
        atomicMax((unsigned*)&seg_tbl[sid * 64 + c],
                  __float_as_uint(fmaxf(m, 0.f)));
    }
    __syncthreads();

    // phase 3b-iii: one global op per (segment, col)
    for (int idx = t; idx < nseg * 64; idx += 256) {
        int s = idx >> 6;
        int c = idx & 63;
        unsigned val = *(unsigned*)&seg_tbl[idx];
        unsigned* dest = (unsigned*)out + (size_t)sdst2[s] * F + c;
        if (s == 0 || s == nseg - 1) atomicMax(dest, val);
        else                         *dest = val;
    }
}

// ===========================================================================
// launch
// ===========================================================================
extern "C" void kernel_launch(void* const* d_in, const int* in_sizes, int n_in,
                              void* d_out, int out_size)
{
    const float* x   = (const float*)d_in[0];
    const int*   ei  = (const int*)d_in[1];
    const float* W1  = (const float*)d_in[2];
    const float* b1  = (const float*)d_in[3];
    const float* W2  = (const float*)d_in[4];
    const float* b2  = (const float*)d_in[5];
    float* out = (float*)d_out;

    float *u, *v, *x1, *x2;
    int *cnt, *part, *run, *bsum, *ssrc, *sdst;
    cudaGetSymbolAddress((void**)&u,    g_u);
    cudaGetSymbolAddress((void**)&v,    g_v);
    cudaGetSymbolAddress((void**)&x1,   g_x1);
    cudaGetSymbolAddress((void**)&x2,   g_x2);
    cudaGetSymbolAddress((void**)&cnt,  g_cnt);
    cudaGetSymbolAddress((void**)&part, g_part);
    cudaGetSymbolAddress((void**)&run,  g_run);
    cudaGetSymbolAddress((void**)&bsum, g_bsum);
    cudaGetSymbolAddress((void**)&ssrc, g_ssrc);
    cudaGetSymbolAddress((void**)&sdst, g_sdst);

    // smem: hbuf 17408 ; W2p 18432 ; b2 256 ; si/di 512 ; misc 16
    const int smem_bytes = TE * PAD * 4 + 32 * WST * 4 + 64 * 4 + 2 * TE * 4 + 16;
    cudaFuncSetAttribute(edge_kernel, cudaFuncAttributeMaxDynamicSharedMemorySize,
                         smem_bytes);

    const int node_blocks = (NN + 31) / 32;       // 1563
    const int edge_blocks = NE / TE;              // 12500
    const int eth_blocks  = NE / 256;             // 3125

    cudaMemsetAsync(cnt, 0, NN * sizeof(int));
    hist_kernel<<<eth_blocks, 256>>>(ei, cnt);
    scan1_kernel<<<NCHUNKS, 256>>>(cnt, part, bsum);
    scan23_kernel<<<1, 256>>>(part, bsum, run);

    const float* cur = x;
    float* bufs[NLAYERS] = {x1, x2, out};

    for (int l = 0; l < NLAYERS; l++) {
        float* y = bufs[l];
        node_kernel<<<node_blocks, 256>>>(cur, W1 + l * 128 * 64, b1 + l * 64,
                                          u, v, y);
        if (l == 0)
            scatter_kernel<<<eth_blocks, 256>>>(ei, run, ssrc, sdst);
        edge_kernel<<<edge_blocks, 256, smem_bytes>>>(ssrc, sdst, u, v,
                                                      W2 + l * 64 * 64,
                                                      b2 + l * 64, y);
        cur = y;
    }
}

// round 13
// speedup vs baseline: 1.0345x; 1.0345x over previous
#include <cuda_runtime.h>
#include <cstdint>

#define NN 50000
#define NE 800000
#define F  64
#define NLAYERS 3
#define NCHUNKS 196     // ceil(NN/256)

#define TE     64       // edges per tile in edge kernel
#define NTILES (NE / TE)    // 12500
#define EBLK   592      // persistent edge blocks (~4 per SM)
#define PAD    68       // h1s/h2n row pad in floats (272B, 16B-aligned)
#define WST    144      // W2p row stride in floats (swizzled)

// ---------------- scratch (device globals; no allocation allowed) ----------
__device__ float g_u [NN * F];
__device__ float g_v [NN * F];
__device__ float g_x1[NN * F];
__device__ float g_x2[NN * F];
__device__ int   g_cnt [NN];
__device__ int   g_part[NN];
__device__ int   g_run [NN];
__device__ int   g_bsum[256];
__device__ int   g_ssrc[NE];
__device__ int   g_sdst[NE];

// ===========================================================================
// Prep: counting sort of edges by dst (once per launch)
// ===========================================================================
__global__ __launch_bounds__(256) void hist_kernel(const int* __restrict__ ei,
                                                   int* __restrict__ cnt)
{
    int e = blockIdx.x * 256 + threadIdx.x;
    atomicAdd(&cnt[ei[NE + e]], 1);
}

__device__ __forceinline__ int block_scan_excl(int v, int t, int* wsum)
{
    int lane = t & 31, w = t >> 5;
    int s = v;
    #pragma unroll
    for (int d = 1; d < 32; d <<= 1) {
        int n = __shfl_up_sync(0xffffffffu, s, d);
        if (lane >= d) s += n;
    }
    if (lane == 31) wsum[w] = s;
    __syncthreads();
    if (w == 0) {
        int ws = (lane < 8) ? wsum[lane] : 0;
        #pragma unroll
        for (int d = 1; d < 8; d <<= 1) {
            int n = __shfl_up_sync(0xffffffffu, ws, d);
            if (lane >= d) ws += n;
        }
        if (lane < 8) wsum[lane] = ws;
    }
    __syncthreads();
    int base = (w > 0) ? wsum[w - 1] : 0;
    return s - v + base;
}

__global__ __launch_bounds__(256) void scan1_kernel(const int* __restrict__ cnt,
                                                    int* __restrict__ part,
                                                    int* __restrict__ bsum)
{
    __shared__ int wsum[8];
    int t = threadIdx.x;
    int i = blockIdx.x * 256 + t;
    int v = (i < NN) ? cnt[i] : 0;
    int ex = block_scan_excl(v, t, wsum);
    if (i < NN) part[i] = ex;
    if (t == 255) bsum[blockIdx.x] = ex + v;
}

__global__ __launch_bounds__(256) void scan23_kernel(const int* __restrict__ part,
                                                     const int* __restrict__ bsum,
                                                     int* __restrict__ run)
{
    __shared__ int wsum[8];
    __shared__ int sb[256];
    int t = threadIdx.x;
    int v = (t < NCHUNKS) ? bsum[t] : 0;
    int ex = block_scan_excl(v, t, wsum);
    sb[t] = ex;
    __syncthreads();
    #pragma unroll 4
    for (int i = t; i < NN; i += 256)
        run[i] = part[i] + sb[i >> 8];
}

__global__ __launch_bounds__(256) void scatter_kernel(const int* __restrict__ ei,
                                                      int* __restrict__ run,
                                                      int* __restrict__ ssrc,
                                                      int* __restrict__ sdst)
{
    int e = blockIdx.x * 256 + threadIdx.x;
    int s = ei[e];
    int d = ei[NE + e];
    int pos = atomicAdd(&run[d], 1);
    ssrc[pos] = s;
    sdst[pos] = d;
}

// ===========================================================================
// Node kernel: u = x@(W1a - W1b) + b1 ;  v = x@W1b  (proven R7/R10 version)
// Also zero-fills a slice of this layer's output buffer y.
// ===========================================================================
__global__ __launch_bounds__(256) void node_kernel(
    const float* __restrict__ x,
    const float* __restrict__ W1,   // [128,64]
    const float* __restrict__ b1g,  // [64]
    float* __restrict__ u,
    float* __restrict__ v,
    float* __restrict__ y)
{
    __shared__ float W1s[128 * 64];
    __shared__ float xs[32 * 64];

    const int t  = threadIdx.x;
    const int n0 = blockIdx.x * 32;

    {
        int base = blockIdx.x * 2048 + t * 8;
        if (base < NN * F) {
            float4 z = make_float4(0.f, 0.f, 0.f, 0.f);
            *(float4*)(y + base)     = z;
            *(float4*)(y + base + 4) = z;
        }
    }

    #pragma unroll
    for (int r = 0; r < 32; r++) W1s[r * 256 + t] = W1[r * 256 + t];

    #pragma unroll
    for (int r = 0; r < 8; r++) {
        int idx  = r * 256 + t;
        int nn   = idx >> 6;
        int f    = idx & 63;
        int node = n0 + nn;
        xs[idx] = (node < NN) ? x[node * F + f] : 0.f;
    }
    __syncthreads();

    const int jc = (t & 31) * 2;
    const int ng = t >> 5;

    unsigned long long accA[4], accC[4];
    #pragma unroll
    for (int s = 0; s < 4; s++) { accA[s] = 0ull; accC[s] = 0ull; }

    #pragma unroll 8
    for (int k = 0; k < F; k++) {
        unsigned long long wa = *(const unsigned long long*)&W1s[k * F + jc];
        unsigned long long wb = *(const unsigned long long*)&W1s[(F + k) * F + jc];
        #pragma unroll
        for (int s = 0; s < 4; s++) {
            float xk = xs[(ng + 8 * s) * F + k];
            unsigned long long hh;
            unsigned hb = __float_as_uint(xk);
            asm("mov.b64 %0, {%1, %1};" : "=l"(hh) : "r"(hb));
            asm("fma.rn.f32x2 %0, %1, %2, %0;" : "+l"(accA[s]) : "l"(hh), "l"(wa));
            asm("fma.rn.f32x2 %0, %1, %2, %0;" : "+l"(accC[s]) : "l"(hh), "l"(wb));
        }
    }

    const float bb0 = b1g[jc], bb1 = b1g[jc + 1];
    #pragma unroll
    for (int s = 0; s < 4; s++) {
        int node = n0 + ng + 8 * s;
        if (node < NN) {
            unsigned a0u, a1u, c0u, c1u;
            asm("mov.b64 {%0, %1}, %2;" : "=r"(a0u), "=r"(a1u) : "l"(accA[s]));
            asm("mov.b64 {%0, %1}, %2;" : "=r"(c0u), "=r"(c1u) : "l"(accC[s]));
            float a0 = __uint_as_float(a0u), a1 = __uint_as_float(a1u);
            float c0 = __uint_as_float(c0u), c1 = __uint_as_float(c1u);
            u[node * F + jc]     = a0 - c0 + bb0;
            u[node * F + jc + 1] = a1 - c1 + bb1;
            v[node * F + jc]     = c0;
            v[node * F + jc + 1] = c1;
        }
    }
}

// ===========================================================================
// Edge kernel — PERSISTENT blocks (EBLK blocks, contiguous tile ranges):
//  W2p/b2 staged ONCE per block; per tile the body is the proven R10 code:
//  phase1 coalesced gather -> phase2 k-pair f32x2 (4x4 tile) -> phase3 serial
//  segmented max + 1 atomicMax per segment.
// ===========================================================================
__global__ __launch_bounds__(256, 4) void edge_kernel(
    const int* __restrict__ ssrc,
    const int* __restrict__ sdst,
    const float* __restrict__ u,
    const float* __restrict__ v,
    const float* __restrict__ W2,       // [64,64]
    const float* __restrict__ b2g,      // [64]
    float* __restrict__ out)
{
    extern __shared__ float smem[];
    float* hbuf = smem;                       // TE*PAD (h1s, then h2n)
    float* W2p  = smem + TE * PAD;            // 32*WST k-pair-interleaved+swizzled
    float* b2s  = W2p + 32 * WST;             // 64
    int*   si   = (int*)(b2s + 64);           // TE
    int*   di   = si + TE;                    // TE

    const int t = threadIdx.x;

    // ---- one-time staging: W2p (swizzled) + b2 ----
    #pragma unroll
    for (int r = 0; r < 4; r++) {
        int j  = r * 256 + t;
        int kk = j >> 4;
        int c0 = (j & 15) * 4;
        float4 w4 = *(const float4*)(W2 + kk * 64 + c0);
        int k2 = kk >> 1, p = kk & 1;
        int cgi = c0 >> 2;
        int base = k2 * WST + cgi * 8 + (cgi >> 2) * 4 + p;
        W2p[base]     = w4.x;
        W2p[base + 2] = w4.y;
        W2p[base + 4] = w4.z;
        W2p[base + 6] = w4.w;
    }
    if (t < 64) b2s[t] = b2g[t];

    const int cg   = t & 15;
    const int eg   = t >> 4;
    const int woff = cg * 8 + (cg >> 2) * 4;

    // contiguous balanced tile range for this block
    const int t0 = (int)((long long)blockIdx.x       * NTILES / EBLK);
    const int t1 = (int)(((long long)blockIdx.x + 1) * NTILES / EBLK);

    for (int tile = t0; tile < t1; tile++) {
        const int e0 = tile * TE;

        if (t < TE)            si[t]      = ssrc[e0 + t];
        else if (t < 2 * TE)   di[t - TE] = sdst[e0 + t - TE];
        __syncthreads();

        // phase 1: h1 = relu(u[dst] + v[src]) -> smem row-major (float4)
        #pragma unroll 4
        for (int r = 0; r < 4; r++) {
            int idx = r * 256 + t;
            int e   = idx >> 4;
            int q   = idx & 15;
            float4 uq = *(const float4*)(u + (size_t)di[e] * F + q * 4);
            float4 vq = *(const float4*)(v + (size_t)si[e] * F + q * 4);
            float4 h;
            h.x = fmaxf(uq.x + vq.x, 0.f);
            h.y = fmaxf(uq.y + vq.y, 0.f);
            h.z = fmaxf(uq.z + vq.z, 0.f);
            h.w = fmaxf(uq.w + vq.w, 0.f);
            *(float4*)&hbuf[e * PAD + q * 4] = h;
        }
        __syncthreads();

        // phase 2: tile = 4 edges x 4 cols, one k-pair per iteration
        unsigned long long acc[4][4];
        #pragma unroll
        for (int i = 0; i < 4; i++)
            #pragma unroll
            for (int c = 0; c < 4; c++)
                acc[i][c] = 0ull;

        const float* hrow = hbuf + eg * 4 * PAD;
        #pragma unroll 4
        for (int k2 = 0; k2 < 32; k2++) {
            unsigned long long hp[4];
            #pragma unroll
            for (int i = 0; i < 4; i++)
                hp[i] = *(const unsigned long long*)&hrow[i * PAD + 2 * k2];

            const float* wr = W2p + k2 * WST + woff;
            ulonglong2 w01 = *(const ulonglong2*)wr;
            ulonglong2 w23 = *(const ulonglong2*)(wr + 4);
            unsigned long long wv[4] = {w01.x, w01.y, w23.x, w23.y};

            #pragma unroll
            for (int i = 0; i < 4; i++)
                #pragma unroll
                for (int c = 0; c < 4; c++)
                    asm("fma.rn.f32x2 %0, %1, %2, %0;"
                        : "+l"(acc[i][c]) : "l"(hp[i]), "l"(wv[c]));
        }

        // phase 3a: h2 = lo + hi + b2 -> overlaid smem h2n[e][PAD]
        __syncthreads();
        #pragma unroll
        for (int i = 0; i < 4; i++) {
            int e = eg * 4 + i;
            float4 o;
            float* op = (float*)&o;
            #pragma unroll
            for (int c = 0; c < 4; c++) {
                unsigned lo, hi;
                asm("mov.b64 {%0, %1}, %2;" : "=r"(lo), "=r"(hi) : "l"(acc[i][c]));
                op[c] = __uint_as_float(lo) + __uint_as_float(hi) + b2s[cg * 4 + c];
            }
            *(float4*)&hbuf[e * PAD + cg * 4] = o;
        }
        __syncthreads();

        // phase 3b: segmented max over dst; thread: col c, rows [g*16, +16)
        {
            const int c  = t & 63;
            const int g  = t >> 6;      // 0..3
            const int r0 = g * 16;
            int   cur = di[r0];
            float m   = hbuf[r0 * PAD + c];
            #pragma unroll 1
            for (int r = r0 + 1; r < r0 + 16; r++) {
                int   d2  = di[r];
                float val = hbuf[r * PAD + c];
                if (d2 != cur) {
                    atomicMax((unsigned*)out + (size_t)cur * F + c,
                              __float_as_uint(fmaxf(m, 0.f)));
                    cur = d2;
                    m   = val;
                } else {
                    m = fmaxf(m, val);
                }
            }
            atomicMax((unsigned*)out + (size_t)cur * F + c,
                      __float_as_uint(fmaxf(m, 0.f)));
        }
        __syncthreads();   // protect si/di + hbuf before next tile
    }
}

// ===========================================================================
// launch
// ===========================================================================
extern "C" void kernel_launch(void* const* d_in, const int* in_sizes, int n_in,
                              void* d_out, int out_size)
{
    const float* x   = (const float*)d_in[0];
    const int*   ei  = (const int*)d_in[1];
    const float* W1  = (const float*)d_in[2];
    const float* b1  = (const float*)d_in[3];
    const float* W2  = (const float*)d_in[4];
    const float* b2  = (const float*)d_in[5];
    float* out = (float*)d_out;

    float *u, *v, *x1, *x2;
    int *cnt, *part, *run, *bsum, *ssrc, *sdst;
    cudaGetSymbolAddress((void**)&u,    g_u);
    cudaGetSymbolAddress((void**)&v,    g_v);
    cudaGetSymbolAddress((void**)&x1,   g_x1);
    cudaGetSymbolAddress((void**)&x2,   g_x2);
    cudaGetSymbolAddress((void**)&cnt,  g_cnt);
    cudaGetSymbolAddress((void**)&part, g_part);
    cudaGetSymbolAddress((void**)&run,  g_run);
    cudaGetSymbolAddress((void**)&bsum, g_bsum);
    cudaGetSymbolAddress((void**)&ssrc, g_ssrc);
    cudaGetSymbolAddress((void**)&sdst, g_sdst);

    // smem: hbuf 64*68*4=17408 ; W2p 32*144*4=18432 ; b2 256 ; si/di 512
    const int smem_bytes = TE * PAD * 4 + 32 * WST * 4 + 64 * 4 + 2 * TE * 4;
    cudaFuncSetAttribute(edge_kernel, cudaFuncAttributeMaxDynamicSharedMemorySize,
                         smem_bytes);

    const int node_blocks = (NN + 31) / 32;       // 1563
    const int eth_blocks  = NE / 256;             // 3125

    cudaMemsetAsync(cnt, 0, NN * sizeof(int));
    hist_kernel<<<eth_blocks, 256>>>(ei, cnt);
    scan1_kernel<<<NCHUNKS, 256>>>(cnt, part, bsum);
    scan23_kernel<<<1, 256>>>(part, bsum, run);

    const float* cur = x;
    float* bufs[NLAYERS] = {x1, x2, out};

    for (int l = 0; l < NLAYERS; l++) {
        float* y = bufs[l];
        node_kernel<<<node_blocks, 256>>>(cur, W1 + l * 128 * 64, b1 + l * 64,
                                          u, v, y);
        if (l == 0)
            scatter_kernel<<<eth_blocks, 256>>>(ei, run, ssrc, sdst);
        edge_kernel<<<EBLK, 256, smem_bytes>>>(ssrc, sdst, u, v,
                                               W2 + l * 64 * 64,
                                               b2 + l * 64, y);
        cur = y;
    }
}